// round 17
// baseline (speedup 1.0000x reference)
#include <cuda_runtime.h>
#include <cuda_fp16.h>
#include <string.h>

#define D128 128
#define H0 64
#define W0 96
#define HW0 (H0 * W0)   // 6144

// BOTH pyramids fp16 (HWD). Offsets: L0 0, L1 786432, L2 983040, L3 1032192.
__device__ __align__(16) __half g_f1h[1044480];
__device__ __align__(16) __half g_f2h[1044480];
__device__ int g_done;

// ---------------------------------------------------------------------------
// Kernel 1: transpose fp32 (D, H*W) -> fp16 (H*W, D), both maps.
// grid (96, 2, 2): x = 8x8 tile, y = 64-ch slice, z = map. Resets g_done.
// ---------------------------------------------------------------------------
__global__ __launch_bounds__(512) void transpose_kernel(const float* __restrict__ f1,
                                                        const float* __restrict__ f2) {
    __shared__ float s0[8][8][64];   // 16KB
    int map = blockIdx.z;
    int cB  = blockIdx.y * 64;
    const float* in = map ? f2 : f1;
    __half* base = map ? g_f2h : g_f1h;
    int tx0 = (blockIdx.x % 12) * 8;
    int ty0 = (blockIdx.x / 12) * 8;
    int t = threadIdx.x;

    if (blockIdx.x == 0 && blockIdx.y == 0 && blockIdx.z == 0 && t == 0) g_done = 0;

    {
        int d  = t >> 3;
        int sl = t & 7;
        const float* src = in + (cB + d) * HW0 + (ty0 + sl) * W0 + tx0;
        float4 v0 = *(const float4*)(src);
        float4 v1 = *(const float4*)(src + 4);
        s0[sl][0][d] = v0.x; s0[sl][1][d] = v0.y; s0[sl][2][d] = v0.z; s0[sl][3][d] = v0.w;
        s0[sl][4][d] = v1.x; s0[sl][5][d] = v1.y; s0[sl][6][d] = v1.z; s0[sl][7][d] = v1.w;
    }
    __syncthreads();

    // write transposed fp16 L0: 64 px x 16 chunks of 4 ch = 1024, 2/thread
#pragma unroll
    for (int i = 0; i < 2; i++) {
        int idx = i * 512 + t;
        int c4 = idx & 15;
        int px = idx >> 4;
        int y = px >> 3, x = px & 7;
        float4 w = *(float4*)&s0[y][x][c4 * 4];
        int go = ((ty0 + y) * W0 + tx0 + x) * D128 + cB + c4 * 4;
        __half2 h0 = __floats2half2_rn(w.x, w.y);
        __half2 h1 = __floats2half2_rn(w.z, w.w);
        uint2 pk = make_uint2(*(unsigned*)&h0, *(unsigned*)&h1);
        *(uint2*)(base + go) = pk;
    }
}

// ---------------------------------------------------------------------------
// Kernel 2: MEGA. Blocks 0..251 = pooling (all levels DIRECT from L0, no
// cascade dependency); blocks 252.. = correlation (R15 structure). corrL0
// blocks run concurrently with pooling; corrL1-3 spin on g_done==252.
// Deadlock-safe: max 252 spinners < resident-block slots.
// ---------------------------------------------------------------------------
__global__ __launch_bounds__(512) void mega_kernel(const float* __restrict__ coords,
                                                   float* __restrict__ out) {
    int b = blockIdx.x;
    int t = threadIdx.x;

    if (b < 252) {
        // --- pooling: 516096 elems (258048 per map), 4 per thread
#pragma unroll
        for (int i = 0; i < 4; i++) {
            int idx = b * 2048 + i * 512 + t;
            int m = (idx >= 258048);
            int ii = m ? idx - 258048 : idx;
            __half* base = m ? g_f2h : g_f1h;
            int lvl, ooff, rel;
            if (ii < 196608)      { lvl = 1; ooff = 786432;  rel = ii; }
            else if (ii < 245760) { lvl = 2; ooff = 983040;  rel = ii - 196608; }
            else                  { lvl = 3; ooff = 1032192; rel = ii - 245760; }
            int c  = rel & 127;
            int pk = rel >> 7;
            int Wl = W0 >> lvl;
            int wo = pk % Wl, ho = pk / Wl;
            int s  = 1 << lvl;
            const __half* src = base + ((ho * s) * W0 + wo * s) * D128 + c;
            float acc = 0.f;
            for (int dy = 0; dy < s; dy++)
                for (int dx = 0; dx < s; dx++)
                    acc += __half2float(src[(dy * W0 + dx) * D128]);
            base[ooff + rel] = __float2half(acc * (1.0f / (float)(s * s)));
        }
        __syncthreads();
        __threadfence();
        if (t == 0) atomicAdd(&g_done, 1);
        return;
    }

    // --- correlation
    int cid = b - 252;
    int g8 = (cid % 148) * 7 + cid / 148;
    if (g8 >= 1020) return;

    int lvl, q;
    if (g8 < 768)       { lvl = 0; q = g8; }
    else if (g8 < 960)  { lvl = 1; q = g8 - 768; }
    else if (g8 < 1008) { lvl = 2; q = g8 - 960; }
    else                { lvl = 3; q = g8 - 1008; }

    int loff, ooff;
    switch (lvl) {
        case 0:  loff = 0;       ooff = 0;      break;
        case 1:  loff = 786432;  ooff = 497664; break;
        case 2:  loff = 983040;  ooff = 622080; break;
        default: loff = 1032192; ooff = 653184; break;
    }
    const int Hl = H0 >> lvl, Wl = W0 >> lvl;

    // pooled levels: wait for all pool blocks (release/acquire via g_done)
    if (lvl != 0) {
        if (t == 0) { while (*(volatile int*)&g_done < 252) { } }
        __syncthreads();
        __threadfence();
    }

    int side = t >> 6;          // pixel 0..7 of the octet
    int tt   = t & 63;
    int p    = 8 * q + side;

    __shared__ float sh_c[8][2];
    __shared__ int   sh_addr[8][104];
    __shared__ float sh_dot[8][104];

    int w2   = tt >> 5;         // warp-within-side 0..1
    int lane = t & 31;
    int sub  = lane & 7;
    int quad = lane >> 3;

    // --- f1 fp16 chunks for this lane (chs 8sub..8sub+7 and 64+8sub..)
    const uint4* f1v = (const uint4*)(g_f1h + loff + p * D128);
    uint4 A0 = f1v[sub];
    uint4 A1 = f1v[8 + sub];

    // --- coords + tap addresses: warps 0..7, one pixel each, warp-local
    if (t < 256) {
        int wpix = t >> 5;      // 0..7
        int pc = 8 * q + wpix;
        int pyc = pc / Wl, pxc = pc - pyc * Wl;
        float cxw, cyw;
        if (lvl == 0) {
            float c = 0.f;
            if (lane < 2) c = coords[lane * HW0 + pc];
            cxw = __shfl_sync(0xffffffffu, c, 0);
            cyw = __shfl_sync(0xffffffffu, c, 1);
        } else {
            // jax.image.resize linear antialias: triangle kernel scale
            // f=2^lvl, normalized by in-range weight sum, then /f.
            int   f    = 1 << lvl;
            float invf = 1.0f / (float)f;
            float sy = ((float)pyc + 0.5f) * (float)f - 0.5f;
            float sx = ((float)pxc + 0.5f) * (float)f - 0.5f;
            int jylo = max(0,      (int)floorf(sy - (float)f) + 1);
            int jyhi = min(H0 - 1, (int)floorf(sy + (float)f));
            int jxlo = max(0,      (int)floorf(sx - (float)f) + 1);
            int jxhi = min(W0 - 1, (int)floorf(sx + (float)f));
            int jx = jxlo + (lane & 15);
            bool okx = (jx <= jxhi);
            float wx = okx ? (1.f - fabsf(sx - (float)jx) * invf) : 0.f;
            float acc0 = 0.f, acc1 = 0.f, ws = 0.f;
            for (int jy = jylo + (lane >> 4); jy <= jyhi; jy += 2) {
                float wy = 1.f - fabsf(sy - (float)jy) * invf;
                float ww = wy * wx;
                if (okx) {
                    acc0 += ww * coords[jy * W0 + jx];
                    acc1 += ww * coords[HW0 + jy * W0 + jx];
                    ws   += ww;
                }
            }
#pragma unroll
            for (int m = 16; m; m >>= 1) {
                acc0 += __shfl_xor_sync(0xffffffffu, acc0, m);
                acc1 += __shfl_xor_sync(0xffffffffu, acc1, m);
                ws   += __shfl_xor_sync(0xffffffffu, ws,   m);
            }
            float inv = invf / ws;
            cxw = acc0 * inv;
            cyw = acc1 * inv;
        }
        if (lane == 0) { sh_c[wpix][0] = cxw; sh_c[wpix][1] = cyw; }

        // tap addresses for this pixel, same warp (uint4 units; pad 100..103)
        int ixw = (int)floorf(cxw);
        int iyw = (int)floorf(cyw);
#pragma unroll
        for (int idx = lane; idx < 104; idx += 32) {
            int ty = idx / 10, tx = idx - ty * 10;
            int gy = min(max(iyw + ty - 4, 0), Hl - 1);
            int gx = min(max(ixw + tx - 4, 0), Wl - 1);
            sh_addr[wpix][idx] = (idx < 100) ? (gy * Wl + gx) * 16 : 0;
        }
    }
    __syncthreads();

    const __half2* ah0 = (const __half2*)&A0;
    const __half2* ah1 = (const __half2*)&A1;
    const uint4* f2base = (const uint4*)(g_f2h + loff);

    // --- 100 corner dots per side: 13 passes x (2 warps x 4 positions)
#pragma unroll
    for (int j = 0; j < 13; j++) {
        int pos = j * 8 + w2 * 4 + quad;     // 0..103 (padded addrs)
        const uint4* qv = f2base + sh_addr[side][pos];
        uint4 r0 = qv[sub];
        uint4 r1 = qv[8 + sub];
        const __half2* qh0 = (const __half2*)&r0;
        const __half2* qh1 = (const __half2*)&r1;
        __half2 acc = __floats2half2_rn(0.f, 0.f);
        acc = __hfma2(ah0[0], qh0[0], acc);
        acc = __hfma2(ah0[1], qh0[1], acc);
        acc = __hfma2(ah0[2], qh0[2], acc);
        acc = __hfma2(ah0[3], qh0[3], acc);
        acc = __hfma2(ah1[0], qh1[0], acc);
        acc = __hfma2(ah1[1], qh1[1], acc);
        acc = __hfma2(ah1[2], qh1[2], acc);
        acc = __hfma2(ah1[3], qh1[3], acc);
        float2 fr = __half22float2(acc);
        float s = fr.x + fr.y;
        s += __shfl_xor_sync(0xffffffffu, s, 1);
        s += __shfl_xor_sync(0xffffffffu, s, 2);
        s += __shfl_xor_sync(0xffffffffu, s, 4);
        if (sub == 0 && pos < 100) sh_dot[side][pos] = s;
    }
    __syncthreads();

    // --- bilinear combine: 648 outputs (81 k x 8 px), 32B-contiguous stores
    for (int idx = t; idx < 648; idx += 512) {
        int k  = idx >> 3;
        int sd = idx & 7;
        float cx2 = sh_c[sd][0], cy2 = sh_c[sd][1];
        int ix2 = (int)floorf(cx2);
        int iy2 = (int)floorf(cy2);
        int dxi = k / 9, dyi = k - dxi * 9;
        float xq = fminf(fmaxf(cx2 + (float)(dxi - 4), 0.f), (float)(Wl - 1));
        float yq = fminf(fmaxf(cy2 + (float)(dyi - 4), 0.f), (float)(Hl - 1));
        float x0f = floorf(xq), y0f = floorf(yq);
        float wx1 = xq - x0f,  wy1 = yq - y0f;
        float wx0 = 1.f - wx1, wy0 = 1.f - wy1;
        int t0x = min(max((int)x0f - ix2 + 4, 0), 9), t1x = min(t0x + 1, 9);
        int t0y = min(max((int)y0f - iy2 + 4, 0), 9), t1y = min(t0y + 1, 9);
        float v = wy0 * (wx0 * sh_dot[sd][t0y * 10 + t0x] + wx1 * sh_dot[sd][t0y * 10 + t1x])
                + wy1 * (wx0 * sh_dot[sd][t1y * 10 + t0x] + wx1 * sh_dot[sd][t1y * 10 + t1x]);
        out[ooff + k * (Hl * Wl) + 8 * q + sd] = v * 0.08838834764831845f;  // 1/sqrt(128)
    }
}

// ---------------------------------------------------------------------------
extern "C" void kernel_launch(void* const* d_in, const int* in_sizes, int n_in,
                              void* d_out, int out_size) {
    const float* f1     = (const float*)d_in[0];
    const float* f2     = (const float*)d_in[1];
    const float* coords = (const float*)d_in[2];
    float* out = (float*)d_out;

    transpose_kernel<<<dim3(96, 2, 2), 512>>>(f1, f2);
    // 252 pool blocks + 1036 corr blocks in one launch
    mega_kernel<<<1288, 512>>>(coords, out);
}